// round 1
// baseline (speedup 1.0000x reference)
#include <cuda_runtime.h>
#include <math.h>

// ---------------- problem constants ----------------
#define NPTS   4096
#define LEVELS 4
#define Gq     7
#define GG     49          // 7*7
#define CCH    128
#define XLD    2408        // 2401 padded to multiple of 8
#define MTOT   (NPTS*LEVELS)   // 16384 rows across levels
#define PIX_TOT 16320      // 96*128 + 48*64 + 24*32 + 12*16

// ---------------- scratch (__device__ globals; no cudaMalloc) ----------------
__device__ __align__(128) float g_fmap[(size_t)PIX_TOT * CCH];       // HWC fmaps, all levels
__device__ __align__(128) float g_X[(size_t)MTOT * XLD];             // corr volumes (padded K)
__device__ __align__(128) float g_H[(size_t)MTOT * 384];             // hidden after gelu
__device__ __align__(128) float g_w1p[(size_t)XLD * 384];            // zero-padded w1

// =====================================================================
// Kernel 1: transpose fmaps [C,H,W] -> [H*W, C] (HWC), all levels packed
// =====================================================================
__global__ void transpose_fmaps_kernel(const float* __restrict__ f0,
                                       const float* __restrict__ f1,
                                       const float* __restrict__ f2,
                                       const float* __restrict__ f3) {
    int p = blockIdx.x;           // global pixel id 0..16319
    int pl, HW;
    const float* src;
    if (p < 12288)      { pl = p;          HW = 12288; src = f0; }
    else if (p < 15360) { pl = p - 12288;  HW = 3072;  src = f1; }
    else if (p < 16128) { pl = p - 15360;  HW = 768;   src = f2; }
    else                { pl = p - 16128;  HW = 192;   src = f3; }
    int c = threadIdx.x;          // 128 threads = channels
    g_fmap[(size_t)p * CCH + c] = src[(size_t)c * HW + pl];
}

// =====================================================================
// Kernel 2: zero-pad w1 [2401,384] -> [2408,384]
// =====================================================================
__global__ void w1pad_kernel(const float* __restrict__ w1) {
    int row = blockIdx.x;   // 0..2407
    for (int c = threadIdx.x; c < 384; c += blockDim.x)
        g_w1p[(size_t)row * 384 + c] = (row < 2401) ? w1[(size_t)row * 384 + c] : 0.f;
}

// =====================================================================
// Kernel 3: correlation volume.
// Block = 256 threads = 4 point-groups of 64.
// Per point: stage tfeat row-block (49x128) and bilinear features (49x128)
// in padded smem, then 49x49x128 GEMM with 7x7 register micro-tiles.
// =====================================================================
#define ROWP 132   // smem row pitch (floats), breaks 512B bank aliasing

__global__ void __launch_bounds__(256) corr_kernel(
    const float* __restrict__ coords,
    const float* __restrict__ t0, const float* __restrict__ t1,
    const float* __restrict__ t2, const float* __restrict__ t3)
{
    extern __shared__ float smem[];
    const int grp  = threadIdx.x >> 6;
    const int gtid = threadIdx.x & 63;
    const int pt   = blockIdx.x * 4 + grp;     // 0..16383, same level within block
    const int lvl  = pt >> 12;
    const int n    = pt & 4095;

    const float* tfp = (lvl == 0) ? t0 : (lvl == 1) ? t1 : (lvl == 2) ? t2 : t3;

    const int Ht[4] = {96, 48, 24, 12};
    const int Wt[4] = {128, 64, 32, 16};
    const int Ot[4] = {0, 12288, 15360, 16128};

    float* sfg = smem + (size_t)grp * (2 * GG * ROWP);
    float* tfg = sfg + GG * ROWP;

    // ---- stage template features: tfeat[lvl][ij, n, c] ----
    for (int idx = gtid; idx < GG * 32; idx += 64) {
        int ij = idx >> 5, c4 = idx & 31;
        float4 v = *(const float4*)(tfp + ((size_t)ij * NPTS + n) * CCH + c4 * 4);
        *(float4*)(tfg + ij * ROWP + c4 * 4) = v;
    }

    // ---- bilinear-sample the 7x7 support grid ----
    const float inv = 1.0f / (float)(1 << lvl);
    const float xl = coords[2 * n]     * inv;
    const float yl = coords[2 * n + 1] * inv;
    const float fx = floorf(xl), fy = floorf(yl);
    const float wx = xl - fx,  wy = yl - fy;
    const int   x0 = (int)fx,  y0 = (int)fy;
    const int   H = Ht[lvl], W = Wt[lvl];
    const float* fb = g_fmap + (size_t)Ot[lvl] * CCH;
    const float w00 = (1.f - wy) * (1.f - wx);
    const float w01 = (1.f - wy) * wx;
    const float w10 = wy * (1.f - wx);
    const float w11 = wy * wx;

    for (int idx = gtid; idx < GG * 32; idx += 64) {
        int hw = idx >> 5, c4 = idx & 31;
        int a = hw / 7, b = hw - a * 7;        // dx index a, dy index b
        int xi = x0 + a - 3;
        int yi = y0 + b - 3;
        float4 acc = make_float4(0.f, 0.f, 0.f, 0.f);
        #define CORNER(YY, XX, WW) do {                                            \
            int yy_ = (YY), xx_ = (XX);                                            \
            if (yy_ >= 0 && yy_ < H && xx_ >= 0 && xx_ < W) {                       \
                float4 v_ = *(const float4*)(fb + ((size_t)yy_ * W + xx_) * CCH + c4 * 4); \
                acc.x += (WW) * v_.x; acc.y += (WW) * v_.y;                         \
                acc.z += (WW) * v_.z; acc.w += (WW) * v_.w;                         \
            } } while (0)
        CORNER(yi,     xi,     w00);
        CORNER(yi,     xi + 1, w01);
        CORNER(yi + 1, xi,     w10);
        CORNER(yi + 1, xi + 1, w11);
        #undef CORNER
        *(float4*)(sfg + hw * ROWP + c4 * 4) = acc;
    }

    __syncthreads();

    // ---- 49x49x128 correlation GEMM: 8x8 thread grid, 7x7 micro-tiles ----
    const int ty = gtid >> 3, tx = gtid & 7;
    float acc[7][7];
    #pragma unroll
    for (int i = 0; i < 7; i++)
        #pragma unroll
        for (int j = 0; j < 7; j++) acc[i][j] = 0.f;

    for (int c4 = 0; c4 < 32; c4++) {
        float4 sv[7], tv[7];
        #pragma unroll
        for (int u = 0; u < 7; u++) {
            int hw = u * 8 + ty; if (hw > 48) hw = 48;
            int ij = u * 8 + tx; if (ij > 48) ij = 48;
            sv[u] = *(const float4*)(sfg + hw * ROWP + c4 * 4);
            tv[u] = *(const float4*)(tfg + ij * ROWP + c4 * 4);
        }
        #pragma unroll
        for (int i = 0; i < 7; i++)
            #pragma unroll
            for (int j = 0; j < 7; j++) {
                acc[i][j] = fmaf(sv[i].x, tv[j].x, acc[i][j]);
                acc[i][j] = fmaf(sv[i].y, tv[j].y, acc[i][j]);
                acc[i][j] = fmaf(sv[i].z, tv[j].z, acc[i][j]);
                acc[i][j] = fmaf(sv[i].w, tv[j].w, acc[i][j]);
            }
    }

    // ---- store X row (col = hw*49 + ij), plus zero K-pad ----
    float* xrow = g_X + (size_t)pt * XLD;
    #pragma unroll
    for (int i = 0; i < 7; i++) {
        int hw = i * 8 + ty;
        if (hw < 49) {
            #pragma unroll
            for (int j = 0; j < 7; j++) {
                int ij = j * 8 + tx;
                if (ij < 49) xrow[hw * 49 + ij] = acc[i][j];
            }
        }
    }
    if (gtid < XLD - 2401) xrow[2401 + gtid] = 0.f;
}

// =====================================================================
// SGEMM 128x128x8, 256 threads, 8x8 micro-tile, double-buffered smem.
// gemm1: H = gelu(X @ w1p + b1)      M=16384 N=384 K=2408
// gemm2: out = H @ w2 + b2 (scatter) M=16384 N=256 K=384
// =====================================================================
__global__ void __launch_bounds__(256) gemm1_kernel(const float* __restrict__ b1) {
    __shared__ float4 As[2][8][32];
    __shared__ float4 Bs[2][8][32];
    const int tid = threadIdx.x;
    const int tx = tid & 15, ty = tid >> 4;
    const int m0 = blockIdx.y * 128, n0 = blockIdx.x * 128;
    const int arow = tid >> 1, akq = (tid & 1) * 4;
    const int brow = tid >> 5, bc4 = tid & 31;

    const float* Aptr = g_X   + (size_t)(m0 + arow) * XLD + akq;
    const float* Bptr = g_w1p + (size_t)brow * 384 + n0 + bc4 * 4;

    float acc[8][8];
    #pragma unroll
    for (int i = 0; i < 8; i++)
        #pragma unroll
        for (int j = 0; j < 8; j++) acc[i][j] = 0.f;

    const int KIT = XLD / 8;  // 301
    float4 ra = *(const float4*)Aptr;
    float4 rb = *(const float4*)Bptr;
    {
        float* asf = (float*)&As[0][0][0];
        asf[(akq + 0) * 128 + arow] = ra.x;
        asf[(akq + 1) * 128 + arow] = ra.y;
        asf[(akq + 2) * 128 + arow] = ra.z;
        asf[(akq + 3) * 128 + arow] = ra.w;
        Bs[0][brow][bc4] = rb;
    }
    __syncthreads();

    for (int kt = 0; kt < KIT; kt++) {
        const int buf = kt & 1;
        if (kt + 1 < KIT) {
            ra = *(const float4*)(Aptr + (kt + 1) * 8);
            rb = *(const float4*)(Bptr + (size_t)(kt + 1) * 8 * 384);
        }
        #pragma unroll
        for (int kk = 0; kk < 8; kk++) {
            float4 a0 = As[buf][kk][ty * 2], a1 = As[buf][kk][ty * 2 + 1];
            float4 b0 = Bs[buf][kk][tx * 2], b1v = Bs[buf][kk][tx * 2 + 1];
            float av[8] = {a0.x, a0.y, a0.z, a0.w, a1.x, a1.y, a1.z, a1.w};
            float bv[8] = {b0.x, b0.y, b0.z, b0.w, b1v.x, b1v.y, b1v.z, b1v.w};
            #pragma unroll
            for (int i = 0; i < 8; i++)
                #pragma unroll
                for (int j = 0; j < 8; j++)
                    acc[i][j] = fmaf(av[i], bv[j], acc[i][j]);
        }
        if (kt + 1 < KIT) {
            const int nb = buf ^ 1;
            float* asf = (float*)&As[nb][0][0];
            asf[(akq + 0) * 128 + arow] = ra.x;
            asf[(akq + 1) * 128 + arow] = ra.y;
            asf[(akq + 2) * 128 + arow] = ra.z;
            asf[(akq + 3) * 128 + arow] = ra.w;
            Bs[nb][brow][bc4] = rb;
        }
        __syncthreads();
    }

    // epilogue: bias + exact gelu
    #pragma unroll
    for (int i = 0; i < 8; i++) {
        int mm = m0 + ty * 8 + i;
        float* hrow = g_H + (size_t)mm * 384 + n0 + tx * 8;
        #pragma unroll
        for (int j4 = 0; j4 < 2; j4++) {
            float4 o;
            float v[4];
            #pragma unroll
            for (int c = 0; c < 4; c++) {
                int nn = n0 + tx * 8 + j4 * 4 + c;
                float x = acc[i][j4 * 4 + c] + b1[nn];
                v[c] = 0.5f * x * (1.0f + erff(x * 0.70710678118654752f));
            }
            o.x = v[0]; o.y = v[1]; o.z = v[2]; o.w = v[3];
            *(float4*)(hrow + j4 * 4) = o;
        }
    }
}

__global__ void __launch_bounds__(256) gemm2_kernel(const float* __restrict__ w2,
                                                    const float* __restrict__ b2,
                                                    float* __restrict__ out) {
    __shared__ float4 As[2][8][32];
    __shared__ float4 Bs[2][8][32];
    const int tid = threadIdx.x;
    const int tx = tid & 15, ty = tid >> 4;
    const int m0 = blockIdx.y * 128, n0 = blockIdx.x * 128;
    const int arow = tid >> 1, akq = (tid & 1) * 4;
    const int brow = tid >> 5, bc4 = tid & 31;

    const float* Aptr = g_H + (size_t)(m0 + arow) * 384 + akq;
    const float* Bptr = w2  + (size_t)brow * 256 + n0 + bc4 * 4;

    float acc[8][8];
    #pragma unroll
    for (int i = 0; i < 8; i++)
        #pragma unroll
        for (int j = 0; j < 8; j++) acc[i][j] = 0.f;

    const int KIT = 384 / 8;  // 48
    float4 ra = *(const float4*)Aptr;
    float4 rb = *(const float4*)Bptr;
    {
        float* asf = (float*)&As[0][0][0];
        asf[(akq + 0) * 128 + arow] = ra.x;
        asf[(akq + 1) * 128 + arow] = ra.y;
        asf[(akq + 2) * 128 + arow] = ra.z;
        asf[(akq + 3) * 128 + arow] = ra.w;
        Bs[0][brow][bc4] = rb;
    }
    __syncthreads();

    for (int kt = 0; kt < KIT; kt++) {
        const int buf = kt & 1;
        if (kt + 1 < KIT) {
            ra = *(const float4*)(Aptr + (kt + 1) * 8);
            rb = *(const float4*)(Bptr + (size_t)(kt + 1) * 8 * 256);
        }
        #pragma unroll
        for (int kk = 0; kk < 8; kk++) {
            float4 a0 = As[buf][kk][ty * 2], a1 = As[buf][kk][ty * 2 + 1];
            float4 b0 = Bs[buf][kk][tx * 2], b1v = Bs[buf][kk][tx * 2 + 1];
            float av[8] = {a0.x, a0.y, a0.z, a0.w, a1.x, a1.y, a1.z, a1.w};
            float bv[8] = {b0.x, b0.y, b0.z, b0.w, b1v.x, b1v.y, b1v.z, b1v.w};
            #pragma unroll
            for (int i = 0; i < 8; i++)
                #pragma unroll
                for (int j = 0; j < 8; j++)
                    acc[i][j] = fmaf(av[i], bv[j], acc[i][j]);
        }
        if (kt + 1 < KIT) {
            const int nb = buf ^ 1;
            float* asf = (float*)&As[nb][0][0];
            asf[(akq + 0) * 128 + arow] = ra.x;
            asf[(akq + 1) * 128 + arow] = ra.y;
            asf[(akq + 2) * 128 + arow] = ra.z;
            asf[(akq + 3) * 128 + arow] = ra.w;
            Bs[nb][brow][bc4] = rb;
        }
        __syncthreads();
    }

    // epilogue: bias + scatter into concat layout out[n, lvl*256 + col]
    #pragma unroll
    for (int i = 0; i < 8; i++) {
        int mm  = m0 + ty * 8 + i;
        int nn_ = mm & 4095;
        int lvl = mm >> 12;
        float* orow = out + (size_t)nn_ * 1024 + lvl * 256 + n0 + tx * 8;
        #pragma unroll
        for (int j4 = 0; j4 < 2; j4++) {
            float4 o;
            o.x = acc[i][j4 * 4 + 0] + b2[n0 + tx * 8 + j4 * 4 + 0];
            o.y = acc[i][j4 * 4 + 1] + b2[n0 + tx * 8 + j4 * 4 + 1];
            o.z = acc[i][j4 * 4 + 2] + b2[n0 + tx * 8 + j4 * 4 + 2];
            o.w = acc[i][j4 * 4 + 3] + b2[n0 + tx * 8 + j4 * 4 + 3];
            *(float4*)(orow + j4 * 4) = o;
        }
    }
}

// =====================================================================
// Host launcher: identify inputs by element count (order-agnostic).
// =====================================================================
extern "C" void kernel_launch(void* const* d_in, const int* in_sizes, int n_in,
                              void* d_out, int out_size) {
    const float *fm[4] = {0, 0, 0, 0}, *tf[4] = {0, 0, 0, 0};
    const float *coords = 0, *w1 = 0, *b1 = 0, *w2 = 0, *b2 = 0;
    int tfc = 0;

    auto isW2Neighbor = [](int s) { return s == 384 || s == 256 || s == 921984; };
    auto isFmNeighbor = [](int s) {
        return s == 1572864 || s == 393216 || s == 24576 || s == 25690112;
    };

    for (int i = 0; i < n_in; i++) {
        int s = in_sizes[i];
        const float* p = (const float*)d_in[i];
        switch (s) {
            case 1572864:  fm[0] = p; break;
            case 393216:   fm[1] = p; break;
            case 24576:    fm[3] = p; break;
            case 25690112: if (tfc < 4) tf[tfc++] = p; break;
            case 8192:     coords = p; break;
            case 921984:   w1 = p; break;
            case 384:      b1 = p; break;
            case 256:      b2 = p; break;
            case 98304: {
                int decided = 0;  // 0 unknown, 1 w2, 2 fmaps2
                if (i > 0) {
                    if (isW2Neighbor(in_sizes[i - 1])) decided = 1;
                    else if (isFmNeighbor(in_sizes[i - 1])) decided = 2;
                }
                if (!decided && i + 1 < n_in) {
                    if (isW2Neighbor(in_sizes[i + 1])) decided = 1;
                    else if (isFmNeighbor(in_sizes[i + 1])) decided = 2;
                }
                if (decided == 1) w2 = p;
                else if (decided == 2) fm[2] = p;
                else { if (!fm[2]) fm[2] = p; else w2 = p; }
            } break;
            default: break;
        }
    }

    float* out = (float*)d_out;

    // corr kernel needs ~202 KB dynamic smem
    static const int CORR_SMEM = 4 * 2 * GG * ROWP * (int)sizeof(float);  // 206,976 B
    cudaFuncSetAttribute(corr_kernel, cudaFuncAttributeMaxDynamicSharedMemorySize,
                         CORR_SMEM);

    transpose_fmaps_kernel<<<PIX_TOT, 128>>>(fm[0], fm[1], fm[2], fm[3]);
    w1pad_kernel<<<XLD, 128>>>(w1);
    corr_kernel<<<MTOT / 4, 256, CORR_SMEM>>>(coords, tf[0], tf[1], tf[2], tf[3]);
    gemm1_kernel<<<dim3(3, 128), 256>>>(b1);
    gemm2_kernel<<<dim3(2, 128), 256>>>(w2, b2, out);
}

// round 4
// speedup vs baseline: 1.6754x; 1.6754x over previous
#include <cuda_runtime.h>
#include <cuda_bf16.h>
#include <math.h>
#include <stdint.h>

// ---------------- problem constants ----------------
#define NPTS   4096
#define GG     49
#define CCH    128
#define KX     2432        // 2401 padded to multiple of 32
#define MTOT   16384       // 4096 pts * 4 levels
#define PIX_TOT 16320
#define NH     384
#define NO     256

// ---------------- scratch ----------------
__device__ __align__(128) float         g_fmap[(size_t)PIX_TOT * CCH];
__device__ __align__(128) __nv_bfloat16 g_Xh[(size_t)MTOT * KX];
__device__ __align__(128) __nv_bfloat16 g_Xl[(size_t)MTOT * KX];
__device__ __align__(128) __nv_bfloat16 g_W1h[(size_t)NH * KX];
__device__ __align__(128) __nv_bfloat16 g_W1l[(size_t)NH * KX];
__device__ __align__(128) __nv_bfloat16 g_Hh[(size_t)MTOT * NH];
__device__ __align__(128) __nv_bfloat16 g_Hl[(size_t)MTOT * NH];
__device__ __align__(128) __nv_bfloat16 g_W2h[(size_t)NO * NH];
__device__ __align__(128) __nv_bfloat16 g_W2l[(size_t)NO * NH];

// single dynamic smem symbol for all kernels
extern __shared__ char dynsm[];

// ---------------- PTX helpers (family-portable only) ----------------
__device__ __forceinline__ uint32_t smem_u32(const void* p) {
    uint32_t a;
    asm("{ .reg .u64 t; cvta.to.shared.u64 t, %1; cvt.u32.u64 %0, t; }"
        : "=r"(a) : "l"(p));
    return a;
}
__device__ __forceinline__ void cp16(uint32_t dst, const void* src) {
    asm volatile("cp.async.cg.shared.global [%0], [%1], 16;" :: "r"(dst), "l"(src));
}
#define CP_COMMIT() asm volatile("cp.async.commit_group;" ::: "memory")
#define CP_WAIT(n)  asm volatile("cp.async.wait_group %0;" :: "n"(n) : "memory")

__device__ __forceinline__ void mma16816(float* d, const uint32_t* a, const uint32_t* b) {
    asm volatile("mma.sync.aligned.m16n8k16.row.col.f32.bf16.bf16.f32 "
        "{%0,%1,%2,%3}, {%4,%5,%6,%7}, {%8,%9}, {%0,%1,%2,%3};"
        : "+f"(d[0]), "+f"(d[1]), "+f"(d[2]), "+f"(d[3])
        : "r"(a[0]), "r"(a[1]), "r"(a[2]), "r"(a[3]), "r"(b[0]), "r"(b[1]));
}

// =====================================================================
// Kernel 1: transpose fmaps [C,H,W] -> [pixel, C]
// =====================================================================
__global__ void transpose_fmaps_kernel(const float* __restrict__ f0,
                                       const float* __restrict__ f1,
                                       const float* __restrict__ f2,
                                       const float* __restrict__ f3) {
    int p = blockIdx.x;
    int pl, HW;
    const float* src;
    if (p < 12288)      { pl = p;          HW = 12288; src = f0; }
    else if (p < 15360) { pl = p - 12288;  HW = 3072;  src = f1; }
    else if (p < 16128) { pl = p - 15360;  HW = 768;   src = f2; }
    else                { pl = p - 16128;  HW = 192;   src = f3; }
    int c = threadIdx.x;
    g_fmap[(size_t)p * CCH + c] = src[(size_t)c * HW + pl];
}

// =====================================================================
// Kernel 2a/2b: transpose+split weights to bf16 hi/lo, [N,K] layout
// =====================================================================
__global__ void w1t_kernel(const float* __restrict__ w1) {
    int n = blockIdx.x;            // 0..383
    for (int k = threadIdx.x; k < KX; k += 256) {
        float v = (k < 2401) ? w1[(size_t)k * NH + n] : 0.f;
        __nv_bfloat16 h = __float2bfloat16(v);
        g_W1h[(size_t)n * KX + k] = h;
        g_W1l[(size_t)n * KX + k] = __float2bfloat16(v - __bfloat162float(h));
    }
}
__global__ void w2t_kernel(const float* __restrict__ w2) {
    int n = blockIdx.x;            // 0..255
    for (int k = threadIdx.x; k < NH; k += 256) {
        float v = w2[(size_t)k * NO + n];
        __nv_bfloat16 h = __float2bfloat16(v);
        g_W2h[(size_t)n * NH + k] = h;
        g_W2l[(size_t)n * NH + k] = __float2bfloat16(v - __bfloat162float(h));
    }
}

// =====================================================================
// Kernel 3: correlation volume (bf16 hi/lo epilogue)
// =====================================================================
#define ROWP 132

__global__ void __launch_bounds__(256) corr_kernel(
    const float* __restrict__ coords,
    const float* __restrict__ t0, const float* __restrict__ t1,
    const float* __restrict__ t2, const float* __restrict__ t3)
{
    float* smem = (float*)dynsm;
    const int grp  = threadIdx.x >> 6;
    const int gtid = threadIdx.x & 63;
    const int pt   = blockIdx.x * 4 + grp;
    const int lvl  = pt >> 12;
    const int n    = pt & 4095;

    const float* tfp = (lvl == 0) ? t0 : (lvl == 1) ? t1 : (lvl == 2) ? t2 : t3;

    const int Ht[4] = {96, 48, 24, 12};
    const int Wt[4] = {128, 64, 32, 16};
    const int Ot[4] = {0, 12288, 15360, 16128};

    float* sfg = smem + (size_t)grp * (2 * GG * ROWP);
    float* tfg = sfg + GG * ROWP;

    for (int idx = gtid; idx < GG * 32; idx += 64) {
        int ij = idx >> 5, c4 = idx & 31;
        float4 v = *(const float4*)(tfp + ((size_t)ij * NPTS + n) * CCH + c4 * 4);
        *(float4*)(tfg + ij * ROWP + c4 * 4) = v;
    }

    const float inv = 1.0f / (float)(1 << lvl);
    const float xq = coords[2 * n]     * inv;
    const float yq = coords[2 * n + 1] * inv;
    const float fx = floorf(xq), fy = floorf(yq);
    const float wx = xq - fx,  wy = yq - fy;
    const int   x0 = (int)fx,  y0 = (int)fy;
    const int   H = Ht[lvl], W = Wt[lvl];
    const float* fb = g_fmap + (size_t)Ot[lvl] * CCH;
    const float w00 = (1.f - wy) * (1.f - wx);
    const float w01 = (1.f - wy) * wx;
    const float w10 = wy * (1.f - wx);
    const float w11 = wy * wx;

    for (int idx = gtid; idx < GG * 32; idx += 64) {
        int hw = idx >> 5, c4 = idx & 31;
        int a = hw / 7, b = hw - a * 7;
        int xi = x0 + a - 3;
        int yi = y0 + b - 3;
        float4 acc = make_float4(0.f, 0.f, 0.f, 0.f);
        #define CORNER(YY, XX, WW) do {                                            \
            int yy_ = (YY), xx_ = (XX);                                            \
            if (yy_ >= 0 && yy_ < H && xx_ >= 0 && xx_ < W) {                      \
                float4 v_ = *(const float4*)(fb + ((size_t)yy_ * W + xx_) * CCH + c4 * 4); \
                acc.x += (WW) * v_.x; acc.y += (WW) * v_.y;                        \
                acc.z += (WW) * v_.z; acc.w += (WW) * v_.w;                        \
            } } while (0)
        CORNER(yi,     xi,     w00);
        CORNER(yi,     xi + 1, w01);
        CORNER(yi + 1, xi,     w10);
        CORNER(yi + 1, xi + 1, w11);
        #undef CORNER
        *(float4*)(sfg + hw * ROWP + c4 * 4) = acc;
    }

    __syncthreads();

    const int ty = gtid >> 3, tx = gtid & 7;
    float acc[7][7];
    #pragma unroll
    for (int i = 0; i < 7; i++)
        #pragma unroll
        for (int j = 0; j < 7; j++) acc[i][j] = 0.f;

    for (int c4 = 0; c4 < 32; c4++) {
        float4 sv[7], tv[7];
        #pragma unroll
        for (int u = 0; u < 7; u++) {
            int hw = u * 8 + ty; if (hw > 48) hw = 48;
            int ij = u * 8 + tx; if (ij > 48) ij = 48;
            sv[u] = *(const float4*)(sfg + hw * ROWP + c4 * 4);
            tv[u] = *(const float4*)(tfg + ij * ROWP + c4 * 4);
        }
        #pragma unroll
        for (int i = 0; i < 7; i++)
            #pragma unroll
            for (int j = 0; j < 7; j++) {
                acc[i][j] = fmaf(sv[i].x, tv[j].x, acc[i][j]);
                acc[i][j] = fmaf(sv[i].y, tv[j].y, acc[i][j]);
                acc[i][j] = fmaf(sv[i].z, tv[j].z, acc[i][j]);
                acc[i][j] = fmaf(sv[i].w, tv[j].w, acc[i][j]);
            }
    }

    __nv_bfloat16* oxh = g_Xh + (size_t)pt * KX;
    __nv_bfloat16* oxl = g_Xl + (size_t)pt * KX;
    #pragma unroll
    for (int i = 0; i < 7; i++) {
        int hw = i * 8 + ty;
        if (hw < 49) {
            #pragma unroll
            for (int j = 0; j < 7; j++) {
                int ij = j * 8 + tx;
                if (ij < 49) {
                    float v = acc[i][j];
                    __nv_bfloat16 h = __float2bfloat16(v);
                    oxh[hw * 49 + ij] = h;
                    oxl[hw * 49 + ij] = __float2bfloat16(v - __bfloat162float(h));
                }
            }
        }
    }
    if (gtid < KX - 2401) {
        oxh[2401 + gtid] = __float2bfloat16(0.f);
        oxl[2401 + gtid] = __float2bfloat16(0.f);
    }
}

// =====================================================================
// mma.sync bf16-split GEMMs.
// CTA tile 128(M) x 128(N), K-tile 32. Per K-tile we stage 4 tiles
// (Ah, Al, Bh, Bl) and accumulate Ah*Bh + Al*Bh + Ah*Bl into one acc.
// smem rows padded to 40 bf16 (80B) -> conflict-free fragment loads.
// 8 warps = 2(M) x 4(N); warp tile 64x32 = 4x4 m16n8k16 fragments.
// =====================================================================
#define ASTR  40
#define TILEB (128 * ASTR * 2)   // 10240 B per tile
#define BUFB  (4 * TILEB)        // 40960 B per buffer
#define GSMEM (2 * BUFB)         // 81920 B total

struct GemmSrc {
    const __nv_bfloat16 *Ah, *Al, *Bh, *Bl;
    int lda, ldb;
};

__device__ __forceinline__ void gemm_load_tiles(uint32_t sb, const GemmSrc& S,
                                                int buf, int kt, int m0, int n0) {
    const int tid = threadIdx.x;
    const int k0 = kt * 32;
    #pragma unroll
    for (int it = 0; it < 8; it++) {
        int cid  = it * 256 + tid;
        int t    = cid >> 9;
        int unit = cid & 511;
        int row  = unit >> 2, seg = unit & 3;
        const __nv_bfloat16* src;
        if (t == 0)      src = S.Ah + (size_t)(m0 + row) * S.lda + k0 + seg * 8;
        else if (t == 1) src = S.Al + (size_t)(m0 + row) * S.lda + k0 + seg * 8;
        else if (t == 2) src = S.Bh + (size_t)(n0 + row) * S.ldb + k0 + seg * 8;
        else             src = S.Bl + (size_t)(n0 + row) * S.ldb + k0 + seg * 8;
        uint32_t dst = sb + buf * BUFB + t * TILEB + row * 80 + seg * 16;
        cp16(dst, src);
    }
}

// core mainloop: accumulates into acc[4][4][4]
__device__ __forceinline__ void gemm_mainloop(uint32_t sb, const GemmSrc& S,
                                              int NT, int m0, int n0,
                                              float acc[4][4][4]) {
    const char* sm = dynsm;
    const int lane = threadIdx.x & 31;
    const int wid  = threadIdx.x >> 5;
    const int wm = (wid >> 2) * 64;
    const int wn = (wid & 3) * 32;
    const int r  = lane >> 2;
    const int cq = (lane & 3) * 2;

    gemm_load_tiles(sb, S, 0, 0, m0, n0);
    CP_COMMIT();

    for (int kt = 0; kt < NT; kt++) {
        const int buf = kt & 1;
        if (kt + 1 < NT) {
            gemm_load_tiles(sb, S, buf ^ 1, kt + 1, m0, n0);
            CP_COMMIT();
            CP_WAIT(1);
        } else {
            CP_WAIT(0);
        }
        __syncthreads();

        const char* p = sm + buf * BUFB;
        #pragma unroll
        for (int ks = 0; ks < 2; ks++) {
            const int kb = (ks * 16 + cq) * 2;
            uint32_t ah[4][4], bh[4][2];
            #pragma unroll
            for (int mi = 0; mi < 4; mi++) {
                int ro = (wm + mi * 16 + r) * 80 + kb;
                ah[mi][0] = *(const uint32_t*)(p + ro);
                ah[mi][1] = *(const uint32_t*)(p + ro + 8 * 80);
                ah[mi][2] = *(const uint32_t*)(p + ro + 16);
                ah[mi][3] = *(const uint32_t*)(p + ro + 8 * 80 + 16);
            }
            const char* pbh = p + 2 * TILEB;
            #pragma unroll
            for (int ni = 0; ni < 4; ni++) {
                int co = (wn + ni * 8 + r) * 80 + kb;
                bh[ni][0] = *(const uint32_t*)(pbh + co);
                bh[ni][1] = *(const uint32_t*)(pbh + co + 16);
            }
            #pragma unroll
            for (int mi = 0; mi < 4; mi++)
                #pragma unroll
                for (int ni = 0; ni < 4; ni++)
                    mma16816(acc[mi][ni], ah[mi], bh[ni]);

            // Ah * Bl
            {
                uint32_t bl[4][2];
                const char* pbl = p + 3 * TILEB;
                #pragma unroll
                for (int ni = 0; ni < 4; ni++) {
                    int co = (wn + ni * 8 + r) * 80 + kb;
                    bl[ni][0] = *(const uint32_t*)(pbl + co);
                    bl[ni][1] = *(const uint32_t*)(pbl + co + 16);
                }
                #pragma unroll
                for (int mi = 0; mi < 4; mi++)
                    #pragma unroll
                    for (int ni = 0; ni < 4; ni++)
                        mma16816(acc[mi][ni], ah[mi], bl[ni]);
            }
            // Al * Bh
            {
                uint32_t al[4][4];
                const char* pal = p + TILEB;
                #pragma unroll
                for (int mi = 0; mi < 4; mi++) {
                    int ro = (wm + mi * 16 + r) * 80 + kb;
                    al[mi][0] = *(const uint32_t*)(pal + ro);
                    al[mi][1] = *(const uint32_t*)(pal + ro + 8 * 80);
                    al[mi][2] = *(const uint32_t*)(pal + ro + 16);
                    al[mi][3] = *(const uint32_t*)(pal + ro + 8 * 80 + 16);
                }
                #pragma unroll
                for (int mi = 0; mi < 4; mi++)
                    #pragma unroll
                    for (int ni = 0; ni < 4; ni++)
                        mma16816(acc[mi][ni], al[mi], bh[ni]);
            }
        }
        __syncthreads();
    }
}

__global__ void __launch_bounds__(256, 2) gemm1_mma(const float* __restrict__ b1) {
    uint32_t sb = smem_u32(dynsm);
    const int m0 = blockIdx.x * 128, n0 = blockIdx.y * 128;
    const int lane = threadIdx.x & 31, wid = threadIdx.x >> 5;
    const int wm = (wid >> 2) * 64, wn = (wid & 3) * 32;
    const int r = lane >> 2, cq = (lane & 3) * 2;

    float acc[4][4][4];
    #pragma unroll
    for (int mi = 0; mi < 4; mi++)
        #pragma unroll
        for (int ni = 0; ni < 4; ni++)
            #pragma unroll
            for (int q = 0; q < 4; q++) acc[mi][ni][q] = 0.f;

    GemmSrc S = {g_Xh, g_Xl, g_W1h, g_W1l, KX, KX};
    gemm_mainloop(sb, S, KX / 32, m0, n0, acc);

    // epilogue: bias + exact gelu, split bf16 hi/lo
    #pragma unroll
    for (int mi = 0; mi < 4; mi++) {
        #pragma unroll
        for (int rr = 0; rr < 2; rr++) {
            int m = m0 + wm + mi * 16 + r + rr * 8;
            #pragma unroll
            for (int ni = 0; ni < 4; ni++) {
                int nn = n0 + wn + ni * 8 + cq;
                float x0 = acc[mi][ni][rr * 2 + 0] + b1[nn];
                float x1 = acc[mi][ni][rr * 2 + 1] + b1[nn + 1];
                float g0 = 0.5f * x0 * (1.0f + erff(x0 * 0.70710678118654752f));
                float g1 = 0.5f * x1 * (1.0f + erff(x1 * 0.70710678118654752f));
                __nv_bfloat16 h0 = __float2bfloat16(g0);
                __nv_bfloat16 h1 = __float2bfloat16(g1);
                __nv_bfloat16 l0 = __float2bfloat16(g0 - __bfloat162float(h0));
                __nv_bfloat16 l1 = __float2bfloat16(g1 - __bfloat162float(h1));
                __nv_bfloat162 ph = __halves2bfloat162(h0, h1);
                __nv_bfloat162 pl = __halves2bfloat162(l0, l1);
                *(uint32_t*)(g_Hh + (size_t)m * NH + nn) = *(uint32_t*)&ph;
                *(uint32_t*)(g_Hl + (size_t)m * NH + nn) = *(uint32_t*)&pl;
            }
        }
    }
}

__global__ void __launch_bounds__(256, 2) gemm2_mma(const float* __restrict__ b2,
                                                    float* __restrict__ out) {
    uint32_t sb = smem_u32(dynsm);
    const int m0 = blockIdx.x * 128, n0 = blockIdx.y * 128;
    const int lane = threadIdx.x & 31, wid = threadIdx.x >> 5;
    const int wm = (wid >> 2) * 64, wn = (wid & 3) * 32;
    const int r = lane >> 2, cq = (lane & 3) * 2;

    float acc[4][4][4];
    #pragma unroll
    for (int mi = 0; mi < 4; mi++)
        #pragma unroll
        for (int ni = 0; ni < 4; ni++)
            #pragma unroll
            for (int q = 0; q < 4; q++) acc[mi][ni][q] = 0.f;

    GemmSrc S = {g_Hh, g_Hl, g_W2h, g_W2l, NH, NH};
    gemm_mainloop(sb, S, NH / 32, m0, n0, acc);

    // epilogue: bias + scatter to out[n, lvl*256 + col]
    #pragma unroll
    for (int mi = 0; mi < 4; mi++) {
        #pragma unroll
        for (int rr = 0; rr < 2; rr++) {
            int m   = m0 + wm + mi * 16 + r + rr * 8;
            int n_  = m & 4095;
            int lvl = m >> 12;
            float* orow = out + (size_t)n_ * 1024 + lvl * 256;
            #pragma unroll
            for (int ni = 0; ni < 4; ni++) {
                int nn = n0 + wn + ni * 8 + cq;
                float2 o;
                o.x = acc[mi][ni][rr * 2 + 0] + b2[nn];
                o.y = acc[mi][ni][rr * 2 + 1] + b2[nn + 1];
                *(float2*)(orow + nn) = o;
            }
        }
    }
}

// =====================================================================
// Host launcher
// =====================================================================
extern "C" void kernel_launch(void* const* d_in, const int* in_sizes, int n_in,
                              void* d_out, int out_size) {
    const float *fm[4] = {0, 0, 0, 0}, *tf[4] = {0, 0, 0, 0};
    const float *coords = 0, *w1 = 0, *b1 = 0, *w2 = 0, *b2 = 0;
    int tfc = 0;

    auto isW2Neighbor = [](int s) { return s == 384 || s == 256 || s == 921984; };
    auto isFmNeighbor = [](int s) {
        return s == 1572864 || s == 393216 || s == 24576 || s == 25690112;
    };

    for (int i = 0; i < n_in; i++) {
        int s = in_sizes[i];
        const float* p = (const float*)d_in[i];
        switch (s) {
            case 1572864:  fm[0] = p; break;
            case 393216:   fm[1] = p; break;
            case 24576:    fm[3] = p; break;
            case 25690112: if (tfc < 4) tf[tfc++] = p; break;
            case 8192:     coords = p; break;
            case 921984:   w1 = p; break;
            case 384:      b1 = p; break;
            case 256:      b2 = p; break;
            case 98304: {
                int decided = 0;
                if (i > 0) {
                    if (isW2Neighbor(in_sizes[i - 1])) decided = 1;
                    else if (isFmNeighbor(in_sizes[i - 1])) decided = 2;
                }
                if (!decided && i + 1 < n_in) {
                    if (isW2Neighbor(in_sizes[i + 1])) decided = 1;
                    else if (isFmNeighbor(in_sizes[i + 1])) decided = 2;
                }
                if (decided == 1) w2 = p;
                else if (decided == 2) fm[2] = p;
                else { if (!fm[2]) fm[2] = p; else w2 = p; }
            } break;
            default: break;
        }
    }

    float* out = (float*)d_out;

    static const int CORR_SMEM = 4 * 2 * GG * ROWP * (int)sizeof(float);
    cudaFuncSetAttribute(corr_kernel, cudaFuncAttributeMaxDynamicSharedMemorySize, CORR_SMEM);
    cudaFuncSetAttribute(gemm1_mma,   cudaFuncAttributeMaxDynamicSharedMemorySize, GSMEM);
    cudaFuncSetAttribute(gemm2_mma,   cudaFuncAttributeMaxDynamicSharedMemorySize, GSMEM);

    transpose_fmaps_kernel<<<PIX_TOT, 128>>>(fm[0], fm[1], fm[2], fm[3]);
    w1t_kernel<<<NH, 256>>>(w1);
    w2t_kernel<<<NO, 256>>>(w2);
    corr_kernel<<<MTOT / 4, 256, CORR_SMEM>>>(coords, tf[0], tf[1], tf[2], tf[3]);
    gemm1_mma<<<dim3(128, 3), 256, GSMEM>>>(b1);
    gemm2_mma<<<dim3(128, 2), 256, GSMEM>>>(b2, out);
}

// round 5
// speedup vs baseline: 2.1401x; 1.2774x over previous
#include <cuda_runtime.h>
#include <cuda_bf16.h>
#include <math.h>
#include <stdint.h>

// ---------------- problem constants ----------------
#define NPTS   4096
#define GG     49
#define CCH    128
#define KX     2432        // 2401 padded to multiple of 32
#define MTOT   16384       // 4096 pts * 4 levels
#define PIX_TOT 16320
#define NH     384
#define NO     256

// ---------------- scratch ----------------
__device__ __align__(128) float         g_fmap[(size_t)PIX_TOT * CCH];
__device__ __align__(128) __nv_bfloat16 g_Xh[(size_t)MTOT * KX];
__device__ __align__(128) __nv_bfloat16 g_Xl[(size_t)MTOT * KX];
__device__ __align__(128) __nv_bfloat16 g_W1h[(size_t)NH * KX];
__device__ __align__(128) __nv_bfloat16 g_W1l[(size_t)NH * KX];
__device__ __align__(128) __nv_bfloat16 g_Hh[(size_t)MTOT * NH];
__device__ __align__(128) __nv_bfloat16 g_Hl[(size_t)MTOT * NH];
__device__ __align__(128) __nv_bfloat16 g_W2h[(size_t)NO * NH];
__device__ __align__(128) __nv_bfloat16 g_W2l[(size_t)NO * NH];

// single dynamic smem symbol for all kernels
extern __shared__ char dynsm[];

// ---------------- PTX helpers (family-portable only) ----------------
__device__ __forceinline__ uint32_t smem_u32(const void* p) {
    uint32_t a;
    asm("{ .reg .u64 t; cvta.to.shared.u64 t, %1; cvt.u32.u64 %0, t; }"
        : "=r"(a) : "l"(p));
    return a;
}
__device__ __forceinline__ void cp16(uint32_t dst, const void* src) {
    asm volatile("cp.async.cg.shared.global [%0], [%1], 16;" :: "r"(dst), "l"(src));
}
#define CP_COMMIT() asm volatile("cp.async.commit_group;" ::: "memory")
#define CP_WAIT(n)  asm volatile("cp.async.wait_group %0;" :: "n"(n) : "memory")

__device__ __forceinline__ void mma16816(float* d, const uint32_t* a, const uint32_t* b) {
    asm volatile("mma.sync.aligned.m16n8k16.row.col.f32.bf16.bf16.f32 "
        "{%0,%1,%2,%3}, {%4,%5,%6,%7}, {%8,%9}, {%0,%1,%2,%3};"
        : "+f"(d[0]), "+f"(d[1]), "+f"(d[2]), "+f"(d[3])
        : "r"(a[0]), "r"(a[1]), "r"(a[2]), "r"(a[3]), "r"(b[0]), "r"(b[1]));
}

// split a float4 into bf16 hi / bf16 lo packed pairs and store (8B each)
__device__ __forceinline__ void split4_store(char* ph, char* pl, float4 v) {
    __nv_bfloat16 h0 = __float2bfloat16(v.x);
    __nv_bfloat16 h1 = __float2bfloat16(v.y);
    __nv_bfloat16 h2 = __float2bfloat16(v.z);
    __nv_bfloat16 h3 = __float2bfloat16(v.w);
    __nv_bfloat162 ha = __halves2bfloat162(h0, h1);
    __nv_bfloat162 hb = __halves2bfloat162(h2, h3);
    *(uint2*)ph = make_uint2(*(uint32_t*)&ha, *(uint32_t*)&hb);
    __nv_bfloat16 l0 = __float2bfloat16(v.x - __bfloat162float(h0));
    __nv_bfloat16 l1 = __float2bfloat16(v.y - __bfloat162float(h1));
    __nv_bfloat16 l2 = __float2bfloat16(v.z - __bfloat162float(h2));
    __nv_bfloat16 l3 = __float2bfloat16(v.w - __bfloat162float(h3));
    __nv_bfloat162 la = __halves2bfloat162(l0, l1);
    __nv_bfloat162 lb = __halves2bfloat162(l2, l3);
    *(uint2*)pl = make_uint2(*(uint32_t*)&la, *(uint32_t*)&lb);
}

// =====================================================================
// Kernel 1: transpose fmaps [C,H,W] -> [pixel, C]
// =====================================================================
__global__ void transpose_fmaps_kernel(const float* __restrict__ f0,
                                       const float* __restrict__ f1,
                                       const float* __restrict__ f2,
                                       const float* __restrict__ f3) {
    int p = blockIdx.x;
    int pl, HW;
    const float* src;
    if (p < 12288)      { pl = p;          HW = 12288; src = f0; }
    else if (p < 15360) { pl = p - 12288;  HW = 3072;  src = f1; }
    else if (p < 16128) { pl = p - 15360;  HW = 768;   src = f2; }
    else                { pl = p - 16128;  HW = 192;   src = f3; }
    int c = threadIdx.x;
    g_fmap[(size_t)p * CCH + c] = src[(size_t)c * HW + pl];
}

// =====================================================================
// Kernel 2a/2b: transpose+split weights to bf16 hi/lo, [N,K] layout
// =====================================================================
__global__ void w1t_kernel(const float* __restrict__ w1) {
    int n = blockIdx.x;            // 0..383
    for (int k = threadIdx.x; k < KX; k += 256) {
        float v = (k < 2401) ? w1[(size_t)k * NH + n] : 0.f;
        __nv_bfloat16 h = __float2bfloat16(v);
        g_W1h[(size_t)n * KX + k] = h;
        g_W1l[(size_t)n * KX + k] = __float2bfloat16(v - __bfloat162float(h));
    }
}
__global__ void w2t_kernel(const float* __restrict__ w2) {
    int n = blockIdx.x;            // 0..255
    for (int k = threadIdx.x; k < NH; k += 256) {
        float v = w2[(size_t)k * NO + n];
        __nv_bfloat16 h = __float2bfloat16(v);
        g_W2h[(size_t)n * NH + k] = h;
        g_W2l[(size_t)n * NH + k] = __float2bfloat16(v - __bfloat162float(h));
    }
}

// =====================================================================
// Kernel 3: correlation volume via mma.sync (bf16 split, 3 passes).
// One CTA (256 thr) per point. smem: A (sampled grid feats) and
// B (tfeat), each bf16 hi/lo, row stride 272B (bank-conflict-free).
// 8 warps = 4 M-frags x 2 N-halves; each warp 64x32 of padded 64x64.
// =====================================================================
#define CSTR  272
#define C_AH  0
#define C_AL  17408
#define C_BH  34816
#define C_BL  52224
#define CSMEM 69632

__global__ void __launch_bounds__(256, 2) corr_tc(
    const float* __restrict__ coords,
    const float* __restrict__ t0, const float* __restrict__ t1,
    const float* __restrict__ t2, const float* __restrict__ t3)
{
    char* sm = dynsm;
    const int tid = threadIdx.x;
    const int pt  = blockIdx.x;
    const int lvl = pt >> 12;
    const int n   = pt & 4095;

    const float* tfp = (lvl == 0) ? t0 : (lvl == 1) ? t1 : (lvl == 2) ? t2 : t3;
    const int Ht[4] = {96, 48, 24, 12};
    const int Wt[4] = {128, 64, 32, 16};
    const int Ot[4] = {0, 12288, 15360, 16128};

    // ---- stage B: tfeat[ij, n, :] -> bf16 hi/lo ----
    for (int idx = tid; idx < GG * 32; idx += 256) {
        int ij = idx >> 5, c4 = idx & 31;
        float4 v = *(const float4*)(tfp + ((size_t)ij * NPTS + n) * CCH + c4 * 4);
        int off = ij * CSTR + c4 * 8;
        split4_store(sm + C_BH + off, sm + C_BL + off, v);
    }

    // ---- stage A: bilinear-sampled support grid -> bf16 hi/lo ----
    const float inv = 1.0f / (float)(1 << lvl);
    const float xq = coords[2 * n]     * inv;
    const float yq = coords[2 * n + 1] * inv;
    const float fx = floorf(xq), fy = floorf(yq);
    const float wx = xq - fx,  wy = yq - fy;
    const int   x0 = (int)fx,  y0 = (int)fy;
    const int   H = Ht[lvl], W = Wt[lvl];
    const float* fb = g_fmap + (size_t)Ot[lvl] * CCH;
    const float w00 = (1.f - wy) * (1.f - wx);
    const float w01 = (1.f - wy) * wx;
    const float w10 = wy * (1.f - wx);
    const float w11 = wy * wx;

    for (int idx = tid; idx < GG * 32; idx += 256) {
        int hw = idx >> 5, c4 = idx & 31;
        int a = hw / 7, b = hw - a * 7;
        int xi = x0 + a - 3;
        int yi = y0 + b - 3;
        float4 acc = make_float4(0.f, 0.f, 0.f, 0.f);
        #define CORNER(YY, XX, WW) do {                                            \
            int yy_ = (YY), xx_ = (XX);                                            \
            if (yy_ >= 0 && yy_ < H && xx_ >= 0 && xx_ < W) {                      \
                float4 v_ = *(const float4*)(fb + ((size_t)yy_ * W + xx_) * CCH + c4 * 4); \
                acc.x += (WW) * v_.x; acc.y += (WW) * v_.y;                        \
                acc.z += (WW) * v_.z; acc.w += (WW) * v_.w;                        \
            } } while (0)
        CORNER(yi,     xi,     w00);
        CORNER(yi,     xi + 1, w01);
        CORNER(yi + 1, xi,     w10);
        CORNER(yi + 1, xi + 1, w11);
        #undef CORNER
        int off = hw * CSTR + c4 * 8;
        split4_store(sm + C_AH + off, sm + C_AL + off, acc);
    }

    __syncthreads();

    // ---- tensor-core 64x64x128 (valid region 49x49) ----
    const int wid = tid >> 5, lane = tid & 31;
    const int mi = wid >> 1;            // M-frag 0..3 (rows mi*16..+15)
    const int nh = wid & 1;             // N-half (cols nh*32..+31)
    const int r  = lane >> 2;
    const int cq2 = (lane & 3) * 2;

    float acc[4][4];
    #pragma unroll
    for (int f = 0; f < 4; f++)
        #pragma unroll
        for (int q = 0; q < 4; q++) acc[f][q] = 0.f;

    const int arow = (mi * 16 + r) * CSTR;
    #pragma unroll
    for (int ks = 0; ks < 8; ks++) {
        const int kb = ks * 32 + cq2 * 2;
        uint32_t ah[4], al[4];
        ah[0] = *(const uint32_t*)(sm + C_AH + arow + kb);
        ah[1] = *(const uint32_t*)(sm + C_AH + arow + 8 * CSTR + kb);
        ah[2] = *(const uint32_t*)(sm + C_AH + arow + kb + 16);
        ah[3] = *(const uint32_t*)(sm + C_AH + arow + 8 * CSTR + kb + 16);
        al[0] = *(const uint32_t*)(sm + C_AL + arow + kb);
        al[1] = *(const uint32_t*)(sm + C_AL + arow + 8 * CSTR + kb);
        al[2] = *(const uint32_t*)(sm + C_AL + arow + kb + 16);
        al[3] = *(const uint32_t*)(sm + C_AL + arow + 8 * CSTR + kb + 16);

        uint32_t bh[4][2], bl[4][2];
        #pragma unroll
        for (int f = 0; f < 4; f++) {
            int brow = (nh * 32 + f * 8 + r) * CSTR + kb;
            bh[f][0] = *(const uint32_t*)(sm + C_BH + brow);
            bh[f][1] = *(const uint32_t*)(sm + C_BH + brow + 16);
            bl[f][0] = *(const uint32_t*)(sm + C_BL + brow);
            bl[f][1] = *(const uint32_t*)(sm + C_BL + brow + 16);
        }
        #pragma unroll
        for (int f = 0; f < 4; f++) {
            mma16816(acc[f], ah, bh[f]);
            mma16816(acc[f], ah, bl[f]);
            mma16816(acc[f], al, bh[f]);
        }
    }

    // ---- epilogue: split to bf16 hi/lo, X row layout col = hw*49 + ij ----
    __nv_bfloat16* oxh = g_Xh + (size_t)pt * KX;
    __nv_bfloat16* oxl = g_Xl + (size_t)pt * KX;
    #pragma unroll
    for (int f = 0; f < 4; f++) {
        int col0 = nh * 32 + f * 8 + cq2;
        #pragma unroll
        for (int rr = 0; rr < 2; rr++) {
            int row = mi * 16 + r + rr * 8;
            if (row < 49) {
                #pragma unroll
                for (int c = 0; c < 2; c++) {
                    int col = col0 + c;
                    if (col < 49) {
                        float v = acc[f][rr * 2 + c];
                        __nv_bfloat16 h = __float2bfloat16(v);
                        oxh[row * 49 + col] = h;
                        oxl[row * 49 + col] = __float2bfloat16(v - __bfloat162float(h));
                    }
                }
            }
        }
    }
    if (tid < KX - 2401) {
        oxh[2401 + tid] = __float2bfloat16(0.f);
        oxl[2401 + tid] = __float2bfloat16(0.f);
    }
}

// =====================================================================
// mma.sync bf16-split GEMMs (unchanged from round 4).
// =====================================================================
#define ASTR  40
#define TILEB (128 * ASTR * 2)   // 10240 B per tile
#define BUFB  (4 * TILEB)        // 40960 B per buffer
#define GSMEM (2 * BUFB)         // 81920 B total

struct GemmSrc {
    const __nv_bfloat16 *Ah, *Al, *Bh, *Bl;
    int lda, ldb;
};

__device__ __forceinline__ void gemm_load_tiles(uint32_t sb, const GemmSrc& S,
                                                int buf, int kt, int m0, int n0) {
    const int tid = threadIdx.x;
    const int k0 = kt * 32;
    #pragma unroll
    for (int it = 0; it < 8; it++) {
        int cid  = it * 256 + tid;
        int t    = cid >> 9;
        int unit = cid & 511;
        int row  = unit >> 2, seg = unit & 3;
        const __nv_bfloat16* src;
        if (t == 0)      src = S.Ah + (size_t)(m0 + row) * S.lda + k0 + seg * 8;
        else if (t == 1) src = S.Al + (size_t)(m0 + row) * S.lda + k0 + seg * 8;
        else if (t == 2) src = S.Bh + (size_t)(n0 + row) * S.ldb + k0 + seg * 8;
        else             src = S.Bl + (size_t)(n0 + row) * S.ldb + k0 + seg * 8;
        uint32_t dst = sb + buf * BUFB + t * TILEB + row * 80 + seg * 16;
        cp16(dst, src);
    }
}

__device__ __forceinline__ void gemm_mainloop(uint32_t sb, const GemmSrc& S,
                                              int NT, int m0, int n0,
                                              float acc[4][4][4]) {
    const char* sm = dynsm;
    const int lane = threadIdx.x & 31;
    const int wid  = threadIdx.x >> 5;
    const int wm = (wid >> 2) * 64;
    const int wn = (wid & 3) * 32;
    const int r  = lane >> 2;
    const int cq = (lane & 3) * 2;

    gemm_load_tiles(sb, S, 0, 0, m0, n0);
    CP_COMMIT();

    for (int kt = 0; kt < NT; kt++) {
        const int buf = kt & 1;
        if (kt + 1 < NT) {
            gemm_load_tiles(sb, S, buf ^ 1, kt + 1, m0, n0);
            CP_COMMIT();
            CP_WAIT(1);
        } else {
            CP_WAIT(0);
        }
        __syncthreads();

        const char* p = sm + buf * BUFB;
        #pragma unroll
        for (int ks = 0; ks < 2; ks++) {
            const int kb = (ks * 16 + cq) * 2;
            uint32_t ah[4][4], bh[4][2];
            #pragma unroll
            for (int mi = 0; mi < 4; mi++) {
                int ro = (wm + mi * 16 + r) * 80 + kb;
                ah[mi][0] = *(const uint32_t*)(p + ro);
                ah[mi][1] = *(const uint32_t*)(p + ro + 8 * 80);
                ah[mi][2] = *(const uint32_t*)(p + ro + 16);
                ah[mi][3] = *(const uint32_t*)(p + ro + 8 * 80 + 16);
            }
            const char* pbh = p + 2 * TILEB;
            #pragma unroll
            for (int ni = 0; ni < 4; ni++) {
                int co = (wn + ni * 8 + r) * 80 + kb;
                bh[ni][0] = *(const uint32_t*)(pbh + co);
                bh[ni][1] = *(const uint32_t*)(pbh + co + 16);
            }
            #pragma unroll
            for (int mi = 0; mi < 4; mi++)
                #pragma unroll
                for (int ni = 0; ni < 4; ni++)
                    mma16816(acc[mi][ni], ah[mi], bh[ni]);

            {
                uint32_t bl[4][2];
                const char* pbl = p + 3 * TILEB;
                #pragma unroll
                for (int ni = 0; ni < 4; ni++) {
                    int co = (wn + ni * 8 + r) * 80 + kb;
                    bl[ni][0] = *(const uint32_t*)(pbl + co);
                    bl[ni][1] = *(const uint32_t*)(pbl + co + 16);
                }
                #pragma unroll
                for (int mi = 0; mi < 4; mi++)
                    #pragma unroll
                    for (int ni = 0; ni < 4; ni++)
                        mma16816(acc[mi][ni], ah[mi], bl[ni]);
            }
            {
                uint32_t al[4][4];
                const char* pal = p + TILEB;
                #pragma unroll
                for (int mi = 0; mi < 4; mi++) {
                    int ro = (wm + mi * 16 + r) * 80 + kb;
                    al[mi][0] = *(const uint32_t*)(pal + ro);
                    al[mi][1] = *(const uint32_t*)(pal + ro + 8 * 80);
                    al[mi][2] = *(const uint32_t*)(pal + ro + 16);
                    al[mi][3] = *(const uint32_t*)(pal + ro + 8 * 80 + 16);
                }
                #pragma unroll
                for (int mi = 0; mi < 4; mi++)
                    #pragma unroll
                    for (int ni = 0; ni < 4; ni++)
                        mma16816(acc[mi][ni], al[mi], bh[ni]);
            }
        }
        __syncthreads();
    }
}

__global__ void __launch_bounds__(256, 2) gemm1_mma(const float* __restrict__ b1) {
    uint32_t sb = smem_u32(dynsm);
    const int m0 = blockIdx.x * 128, n0 = blockIdx.y * 128;
    const int lane = threadIdx.x & 31, wid = threadIdx.x >> 5;
    const int wm = (wid >> 2) * 64, wn = (wid & 3) * 32;
    const int r = lane >> 2, cq = (lane & 3) * 2;

    float acc[4][4][4];
    #pragma unroll
    for (int mi = 0; mi < 4; mi++)
        #pragma unroll
        for (int ni = 0; ni < 4; ni++)
            #pragma unroll
            for (int q = 0; q < 4; q++) acc[mi][ni][q] = 0.f;

    GemmSrc S = {g_Xh, g_Xl, g_W1h, g_W1l, KX, KX};
    gemm_mainloop(sb, S, KX / 32, m0, n0, acc);

    #pragma unroll
    for (int mi = 0; mi < 4; mi++) {
        #pragma unroll
        for (int rr = 0; rr < 2; rr++) {
            int m = m0 + wm + mi * 16 + r + rr * 8;
            #pragma unroll
            for (int ni = 0; ni < 4; ni++) {
                int nn = n0 + wn + ni * 8 + cq;
                float x0 = acc[mi][ni][rr * 2 + 0] + b1[nn];
                float x1 = acc[mi][ni][rr * 2 + 1] + b1[nn + 1];
                float g0 = 0.5f * x0 * (1.0f + erff(x0 * 0.70710678118654752f));
                float g1 = 0.5f * x1 * (1.0f + erff(x1 * 0.70710678118654752f));
                __nv_bfloat16 h0 = __float2bfloat16(g0);
                __nv_bfloat16 h1 = __float2bfloat16(g1);
                __nv_bfloat16 l0 = __float2bfloat16(g0 - __bfloat162float(h0));
                __nv_bfloat16 l1 = __float2bfloat16(g1 - __bfloat162float(h1));
                __nv_bfloat162 ph = __halves2bfloat162(h0, h1);
                __nv_bfloat162 pl = __halves2bfloat162(l0, l1);
                *(uint32_t*)(g_Hh + (size_t)m * NH + nn) = *(uint32_t*)&ph;
                *(uint32_t*)(g_Hl + (size_t)m * NH + nn) = *(uint32_t*)&pl;
            }
        }
    }
}

__global__ void __launch_bounds__(256, 2) gemm2_mma(const float* __restrict__ b2,
                                                    float* __restrict__ out) {
    uint32_t sb = smem_u32(dynsm);
    const int m0 = blockIdx.x * 128, n0 = blockIdx.y * 128;
    const int lane = threadIdx.x & 31, wid = threadIdx.x >> 5;
    const int wm = (wid >> 2) * 64, wn = (wid & 3) * 32;
    const int r = lane >> 2, cq = (lane & 3) * 2;

    float acc[4][4][4];
    #pragma unroll
    for (int mi = 0; mi < 4; mi++)
        #pragma unroll
        for (int ni = 0; ni < 4; ni++)
            #pragma unroll
            for (int q = 0; q < 4; q++) acc[mi][ni][q] = 0.f;

    GemmSrc S = {g_Hh, g_Hl, g_W2h, g_W2l, NH, NH};
    gemm_mainloop(sb, S, NH / 32, m0, n0, acc);

    #pragma unroll
    for (int mi = 0; mi < 4; mi++) {
        #pragma unroll
        for (int rr = 0; rr < 2; rr++) {
            int m   = m0 + wm + mi * 16 + r + rr * 8;
            int n_  = m & 4095;
            int lvl = m >> 12;
            float* orow = out + (size_t)n_ * 1024 + lvl * 256;
            #pragma unroll
            for (int ni = 0; ni < 4; ni++) {
                int nn = n0 + wn + ni * 8 + cq;
                float2 o;
                o.x = acc[mi][ni][rr * 2 + 0] + b2[nn];
                o.y = acc[mi][ni][rr * 2 + 1] + b2[nn + 1];
                *(float2*)(orow + nn) = o;
            }
        }
    }
}

// =====================================================================
// Host launcher
// =====================================================================
extern "C" void kernel_launch(void* const* d_in, const int* in_sizes, int n_in,
                              void* d_out, int out_size) {
    const float *fm[4] = {0, 0, 0, 0}, *tf[4] = {0, 0, 0, 0};
    const float *coords = 0, *w1 = 0, *b1 = 0, *w2 = 0, *b2 = 0;
    int tfc = 0;

    auto isW2Neighbor = [](int s) { return s == 384 || s == 256 || s == 921984; };
    auto isFmNeighbor = [](int s) {
        return s == 1572864 || s == 393216 || s == 24576 || s == 25690112;
    };

    for (int i = 0; i < n_in; i++) {
        int s = in_sizes[i];
        const float* p = (const float*)d_in[i];
        switch (s) {
            case 1572864:  fm[0] = p; break;
            case 393216:   fm[1] = p; break;
            case 24576:    fm[3] = p; break;
            case 25690112: if (tfc < 4) tf[tfc++] = p; break;
            case 8192:     coords = p; break;
            case 921984:   w1 = p; break;
            case 384:      b1 = p; break;
            case 256:      b2 = p; break;
            case 98304: {
                int decided = 0;
                if (i > 0) {
                    if (isW2Neighbor(in_sizes[i - 1])) decided = 1;
                    else if (isFmNeighbor(in_sizes[i - 1])) decided = 2;
                }
                if (!decided && i + 1 < n_in) {
                    if (isW2Neighbor(in_sizes[i + 1])) decided = 1;
                    else if (isFmNeighbor(in_sizes[i + 1])) decided = 2;
                }
                if (decided == 1) w2 = p;
                else if (decided == 2) fm[2] = p;
                else { if (!fm[2]) fm[2] = p; else w2 = p; }
            } break;
            default: break;
        }
    }

    float* out = (float*)d_out;

    cudaFuncSetAttribute(corr_tc,   cudaFuncAttributeMaxDynamicSharedMemorySize, CSMEM);
    cudaFuncSetAttribute(gemm1_mma, cudaFuncAttributeMaxDynamicSharedMemorySize, GSMEM);
    cudaFuncSetAttribute(gemm2_mma, cudaFuncAttributeMaxDynamicSharedMemorySize, GSMEM);

    transpose_fmaps_kernel<<<PIX_TOT, 128>>>(fm[0], fm[1], fm[2], fm[3]);
    w1t_kernel<<<NH, 256>>>(w1);
    w2t_kernel<<<NO, 256>>>(w2);
    corr_tc<<<MTOT, 256, CSMEM>>>(coords, tf[0], tf[1], tf[2], tf[3]);
    gemm1_mma<<<dim3(128, 3), 256, GSMEM>>>(b1);
    gemm2_mma<<<dim3(128, 2), 256, GSMEM>>>(b2, out);
}

// round 7
// speedup vs baseline: 2.1869x; 1.0219x over previous
#include <cuda_runtime.h>
#include <cuda_bf16.h>
#include <math.h>
#include <stdint.h>

// ---------------- problem constants ----------------
#define NPTS   4096
#define GG     49
#define CCH    128
#define KX     2432        // 2401 padded to multiple of 32
#define MTOT   16384       // 4096 pts * 4 levels
#define PIX_TOT 16320
#define NH     384
#define NO     256

// ---------------- scratch ----------------
__device__ __align__(128) float         g_fmap[(size_t)PIX_TOT * CCH];
__device__ __align__(128) __nv_bfloat16 g_Xh[(size_t)MTOT * KX];
__device__ __align__(128) __nv_bfloat16 g_Xl[(size_t)MTOT * KX];
__device__ __align__(128) __nv_bfloat16 g_W1h[(size_t)NH * KX];
__device__ __align__(128) __nv_bfloat16 g_W1l[(size_t)NH * KX];
__device__ __align__(128) __nv_bfloat16 g_Hh[(size_t)MTOT * NH];
__device__ __align__(128) __nv_bfloat16 g_Hl[(size_t)MTOT * NH];
__device__ __align__(128) __nv_bfloat16 g_W2h[(size_t)NO * NH];
__device__ __align__(128) __nv_bfloat16 g_W2l[(size_t)NO * NH];

// single dynamic smem symbol for all kernels
extern __shared__ char dynsm[];

// ---------------- PTX helpers (family-portable only) ----------------
__device__ __forceinline__ uint32_t smem_u32(const void* p) {
    uint32_t a;
    asm("{ .reg .u64 t; cvta.to.shared.u64 t, %1; cvt.u32.u64 %0, t; }"
        : "=r"(a) : "l"(p));
    return a;
}
__device__ __forceinline__ void cp16(uint32_t dst, const void* src) {
    asm volatile("cp.async.cg.shared.global [%0], [%1], 16;" :: "r"(dst), "l"(src));
}
#define CP_COMMIT() asm volatile("cp.async.commit_group;" ::: "memory")
#define CP_WAIT(n)  asm volatile("cp.async.wait_group %0;" :: "n"(n) : "memory")

__device__ __forceinline__ void mma16816(float* d, const uint32_t* a, const uint32_t* b) {
    asm volatile("mma.sync.aligned.m16n8k16.row.col.f32.bf16.bf16.f32 "
        "{%0,%1,%2,%3}, {%4,%5,%6,%7}, {%8,%9}, {%0,%1,%2,%3};"
        : "+f"(d[0]), "+f"(d[1]), "+f"(d[2]), "+f"(d[3])
        : "r"(a[0]), "r"(a[1]), "r"(a[2]), "r"(a[3]), "r"(b[0]), "r"(b[1]));
}
__device__ __forceinline__ void ldsm_x4(uint32_t* r, uint32_t addr) {
    asm volatile("ldmatrix.sync.aligned.m8n8.x4.shared.b16 {%0,%1,%2,%3}, [%4];"
        : "=r"(r[0]), "=r"(r[1]), "=r"(r[2]), "=r"(r[3]) : "r"(addr));
}

// split a float4 into bf16 hi / bf16 lo packed pairs and store (8B each)
__device__ __forceinline__ void split4_store(char* ph, char* pl, float4 v) {
    __nv_bfloat16 h0 = __float2bfloat16(v.x);
    __nv_bfloat16 h1 = __float2bfloat16(v.y);
    __nv_bfloat16 h2 = __float2bfloat16(v.z);
    __nv_bfloat16 h3 = __float2bfloat16(v.w);
    __nv_bfloat162 ha = __halves2bfloat162(h0, h1);
    __nv_bfloat162 hb = __halves2bfloat162(h2, h3);
    *(uint2*)ph = make_uint2(*(uint32_t*)&ha, *(uint32_t*)&hb);
    __nv_bfloat16 l0 = __float2bfloat16(v.x - __bfloat162float(h0));
    __nv_bfloat16 l1 = __float2bfloat16(v.y - __bfloat162float(h1));
    __nv_bfloat16 l2 = __float2bfloat16(v.z - __bfloat162float(h2));
    __nv_bfloat16 l3 = __float2bfloat16(v.w - __bfloat162float(h3));
    __nv_bfloat162 la = __halves2bfloat162(l0, l1);
    __nv_bfloat162 lb = __halves2bfloat162(l2, l3);
    *(uint2*)pl = make_uint2(*(uint32_t*)&la, *(uint32_t*)&lb);
}

// =====================================================================
// Kernel 1 (fused prep): fmap transpose + w1/w2 transpose-split
// =====================================================================
__global__ void prep_kernel(const float* __restrict__ f0, const float* __restrict__ f1,
                            const float* __restrict__ f2, const float* __restrict__ f3,
                            const float* __restrict__ w1, const float* __restrict__ w2) {
    const int bid = blockIdx.x, tid = threadIdx.x;
    if (bid < PIX_TOT / 2) {
        int p = bid * 2 + (tid >> 7);
        int c = tid & 127;
        int pl, HW;
        const float* src;
        if (p < 12288)      { pl = p;          HW = 12288; src = f0; }
        else if (p < 15360) { pl = p - 12288;  HW = 3072;  src = f1; }
        else if (p < 16128) { pl = p - 15360;  HW = 768;   src = f2; }
        else                { pl = p - 16128;  HW = 192;   src = f3; }
        g_fmap[(size_t)p * CCH + c] = src[(size_t)c * HW + pl];
    } else if (bid < PIX_TOT / 2 + NH) {
        int n = bid - PIX_TOT / 2;
        for (int k = tid; k < KX; k += 256) {
            float v = (k < 2401) ? w1[(size_t)k * NH + n] : 0.f;
            __nv_bfloat16 h = __float2bfloat16(v);
            g_W1h[(size_t)n * KX + k] = h;
            g_W1l[(size_t)n * KX + k] = __float2bfloat16(v - __bfloat162float(h));
        }
    } else {
        int n = bid - PIX_TOT / 2 - NH;
        for (int k = tid; k < NH; k += 256) {
            float v = w2[(size_t)k * NO + n];
            __nv_bfloat16 h = __float2bfloat16(v);
            g_W2h[(size_t)n * NH + k] = h;
            g_W2l[(size_t)n * NH + k] = __float2bfloat16(v - __bfloat162float(h));
        }
    }
}

// =====================================================================
// Kernel 2: correlation volume via mma.sync (bf16 split, 3 passes).
// One CTA (256 thr) per point; ldmatrix fragment loads.
// Arrays are 64 rows x 272B (frag reads touch padded rows up to 63).
// =====================================================================
#define CSTR  272
#define C_AH  0
#define C_AL  17408
#define C_BH  34816
#define C_BL  52224
#define CSMEM 69632

__global__ void __launch_bounds__(256, 2) corr_tc(
    const float* __restrict__ coords,
    const float* __restrict__ t0, const float* __restrict__ t1,
    const float* __restrict__ t2, const float* __restrict__ t3)
{
    char* sm = dynsm;
    const int tid = threadIdx.x;
    const int pt  = blockIdx.x;
    const int lvl = pt >> 12;
    const int n   = pt & 4095;

    const float* tfp = (lvl == 0) ? t0 : (lvl == 1) ? t1 : (lvl == 2) ? t2 : t3;
    const int Ht[4] = {96, 48, 24, 12};
    const int Wt[4] = {128, 64, 32, 16};
    const int Ot[4] = {0, 12288, 15360, 16128};

    // ---- stage B: tfeat[ij, n, :] -> bf16 hi/lo ----
    for (int idx = tid; idx < GG * 32; idx += 256) {
        int ij = idx >> 5, c4 = idx & 31;
        float4 v = *(const float4*)(tfp + ((size_t)ij * NPTS + n) * CCH + c4 * 4);
        int off = ij * CSTR + c4 * 8;
        split4_store(sm + C_BH + off, sm + C_BL + off, v);
    }

    // ---- stage A: bilinear-sampled support grid -> bf16 hi/lo ----
    const float inv = 1.0f / (float)(1 << lvl);
    const float xq = coords[2 * n]     * inv;
    const float yq = coords[2 * n + 1] * inv;
    const float fx = floorf(xq), fy = floorf(yq);
    const float wx = xq - fx,  wy = yq - fy;
    const int   x0 = (int)fx,  y0 = (int)fy;
    const int   H = Ht[lvl], W = Wt[lvl];
    const float* fb = g_fmap + (size_t)Ot[lvl] * CCH;
    const float w00 = (1.f - wy) * (1.f - wx);
    const float w01 = (1.f - wy) * wx;
    const float w10 = wy * (1.f - wx);
    const float w11 = wy * wx;

    for (int idx = tid; idx < GG * 32; idx += 256) {
        int hw = idx >> 5, c4 = idx & 31;
        int a = hw / 7, b = hw - a * 7;
        int xi = x0 + a - 3;
        int yi = y0 + b - 3;
        float4 acc = make_float4(0.f, 0.f, 0.f, 0.f);
        #define CORNER(YY, XX, WW) do {                                            \
            int yy_ = (YY), xx_ = (XX);                                            \
            if (yy_ >= 0 && yy_ < H && xx_ >= 0 && xx_ < W) {                      \
                float4 v_ = *(const float4*)(fb + ((size_t)yy_ * W + xx_) * CCH + c4 * 4); \
                acc.x += (WW) * v_.x; acc.y += (WW) * v_.y;                        \
                acc.z += (WW) * v_.z; acc.w += (WW) * v_.w;                        \
            } } while (0)
        CORNER(yi,     xi,     w00);
        CORNER(yi,     xi + 1, w01);
        CORNER(yi + 1, xi,     w10);
        CORNER(yi + 1, xi + 1, w11);
        #undef CORNER
        int off = hw * CSTR + c4 * 8;
        split4_store(sm + C_AH + off, sm + C_AL + off, acc);
    }

    __syncthreads();

    // ---- tensor-core 64x64x128 (valid region 49x49), ldmatrix frags ----
    const uint32_t sb = smem_u32(sm);
    const int wid = tid >> 5, lane = tid & 31;
    const int mi = wid >> 1;            // M-frag 0..3
    const int nh = wid & 1;             // N-half
    const int lrow = lane & 7;
    // A x4 lane map: groups (m+0,k+0),(m+8,k+0),(m+0,k+16B),(m+8,k+16B)
    const uint32_t a_lane = ((((lane >> 3) & 1) * 8 + lrow) * CSTR) + ((lane >> 4) * 16);
    // B x4 lane map: groups (n+0,k+0),(n+0,k+16B),(n+8,k+0),(n+8,k+16B)
    const uint32_t b_lane = (((lane >> 4) * 8 + lrow) * CSTR) + (((lane >> 3) & 1) * 16);

    const uint32_t aH = sb + C_AH + (mi * 16) * CSTR + a_lane;
    const uint32_t aL = sb + C_AL + (mi * 16) * CSTR + a_lane;
    const uint32_t bH = sb + C_BH + (nh * 32) * CSTR + b_lane;
    const uint32_t bL = sb + C_BL + (nh * 32) * CSTR + b_lane;

    float acc[4][4];
    #pragma unroll
    for (int f = 0; f < 4; f++)
        #pragma unroll
        for (int q = 0; q < 4; q++) acc[f][q] = 0.f;

    #pragma unroll
    for (int ks = 0; ks < 8; ks++) {
        const int kb = ks * 32;
        uint32_t ah[4], al[4], bh[2][4], bl[2][4];
        ldsm_x4(ah, aH + kb);
        ldsm_x4(al, aL + kb);
        ldsm_x4(bh[0], bH + kb);
        ldsm_x4(bh[1], bH + 16 * CSTR + kb);
        ldsm_x4(bl[0], bL + kb);
        ldsm_x4(bl[1], bL + 16 * CSTR + kb);
        #pragma unroll
        for (int f = 0; f < 4; f++) {
            const uint32_t* pbh = &bh[f >> 1][(f & 1) * 2];
            const uint32_t* pbl = &bl[f >> 1][(f & 1) * 2];
            mma16816(acc[f], ah, pbh);
            mma16816(acc[f], ah, pbl);
            mma16816(acc[f], al, pbh);
        }
    }

    // ---- epilogue: split to bf16 hi/lo, X row layout col = hw*49 + ij ----
    const int r = lane >> 2;
    const int cq2 = (lane & 3) * 2;
    __nv_bfloat16* oxh = g_Xh + (size_t)pt * KX;
    __nv_bfloat16* oxl = g_Xl + (size_t)pt * KX;
    #pragma unroll
    for (int f = 0; f < 4; f++) {
        int col0 = nh * 32 + f * 8 + cq2;
        #pragma unroll
        for (int rr = 0; rr < 2; rr++) {
            int row = mi * 16 + r + rr * 8;
            if (row < 49) {
                #pragma unroll
                for (int c = 0; c < 2; c++) {
                    int col = col0 + c;
                    if (col < 49) {
                        float v = acc[f][rr * 2 + c];
                        __nv_bfloat16 h = __float2bfloat16(v);
                        oxh[row * 49 + col] = h;
                        oxl[row * 49 + col] = __float2bfloat16(v - __bfloat162float(h));
                    }
                }
            }
        }
    }
    if (tid < KX - 2401) {
        oxh[2401 + tid] = __float2bfloat16(0.f);
        oxl[2401 + tid] = __float2bfloat16(0.f);
    }
}

// =====================================================================
// mma.sync bf16-split GEMMs, ldmatrix fragment loads.
// =====================================================================
#define ASTR  40
#define TILEB (128 * ASTR * 2)   // 10240 B per tile
#define BUFB  (4 * TILEB)        // 40960 B per buffer
#define GSMEM (2 * BUFB)         // 81920 B total

struct GemmSrc {
    const __nv_bfloat16 *Ah, *Al, *Bh, *Bl;
    int lda, ldb;
};

__device__ __forceinline__ void gemm_load_tiles(uint32_t sb, const GemmSrc& S,
                                                int buf, int kt, int m0, int n0) {
    const int tid = threadIdx.x;
    const int k0 = kt * 32;
    #pragma unroll
    for (int it = 0; it < 8; it++) {
        int cid  = it * 256 + tid;
        int t    = cid >> 9;
        int unit = cid & 511;
        int row  = unit >> 2, seg = unit & 3;
        const __nv_bfloat16* src;
        if (t == 0)      src = S.Ah + (size_t)(m0 + row) * S.lda + k0 + seg * 8;
        else if (t == 1) src = S.Al + (size_t)(m0 + row) * S.lda + k0 + seg * 8;
        else if (t == 2) src = S.Bh + (size_t)(n0 + row) * S.ldb + k0 + seg * 8;
        else             src = S.Bl + (size_t)(n0 + row) * S.ldb + k0 + seg * 8;
        uint32_t dst = sb + buf * BUFB + t * TILEB + row * 80 + seg * 16;
        cp16(dst, src);
    }
}

__device__ __forceinline__ void gemm_mainloop(uint32_t sb, const GemmSrc& S,
                                              int NT, int m0, int n0,
                                              float acc[4][4][4]) {
    const int lane = threadIdx.x & 31;
    const int wid  = threadIdx.x >> 5;
    const int wm = (wid >> 2) * 64;
    const int wn = (wid & 3) * 32;
    const int lrow = lane & 7;
    const uint32_t a_lane = ((((lane >> 3) & 1) * 8 + lrow) * 80) + ((lane >> 4) * 16);
    const uint32_t b_lane = (((lane >> 4) * 8 + lrow) * 80) + (((lane >> 3) & 1) * 16);

    gemm_load_tiles(sb, S, 0, 0, m0, n0);
    CP_COMMIT();

    for (int kt = 0; kt < NT; kt++) {
        const int buf = kt & 1;
        if (kt + 1 < NT) {
            gemm_load_tiles(sb, S, buf ^ 1, kt + 1, m0, n0);
            CP_COMMIT();
            CP_WAIT(1);
        } else {
            CP_WAIT(0);
        }
        __syncthreads();

        const uint32_t p = sb + buf * BUFB;
        #pragma unroll
        for (int ks = 0; ks < 2; ks++) {
            const int kb = ks * 32;
            uint32_t bh[2][4], bl[2][4];
            ldsm_x4(bh[0], p + 2 * TILEB + wn * 80 + b_lane + kb);
            ldsm_x4(bh[1], p + 2 * TILEB + (wn + 16) * 80 + b_lane + kb);
            ldsm_x4(bl[0], p + 3 * TILEB + wn * 80 + b_lane + kb);
            ldsm_x4(bl[1], p + 3 * TILEB + (wn + 16) * 80 + b_lane + kb);
            #pragma unroll
            for (int mi = 0; mi < 4; mi++) {
                uint32_t ah[4], al[4];
                ldsm_x4(ah, p + (wm + mi * 16) * 80 + a_lane + kb);
                ldsm_x4(al, p + TILEB + (wm + mi * 16) * 80 + a_lane + kb);
                #pragma unroll
                for (int ni = 0; ni < 4; ni++) {
                    const uint32_t* pbh = &bh[ni >> 1][(ni & 1) * 2];
                    const uint32_t* pbl = &bl[ni >> 1][(ni & 1) * 2];
                    mma16816(acc[mi][ni], ah, pbh);
                    mma16816(acc[mi][ni], ah, pbl);
                    mma16816(acc[mi][ni], al, pbh);
                }
            }
        }
        __syncthreads();
    }
}

__global__ void __launch_bounds__(256, 2) gemm1_mma(const float* __restrict__ b1) {
    uint32_t sb = smem_u32(dynsm);
    const int m0 = blockIdx.y * 128, n0 = blockIdx.x * 128;
    const int lane = threadIdx.x & 31, wid = threadIdx.x >> 5;
    const int wm = (wid >> 2) * 64, wn = (wid & 3) * 32;
    const int r = lane >> 2, cq = (lane & 3) * 2;

    float acc[4][4][4];
    #pragma unroll
    for (int mi = 0; mi < 4; mi++)
        #pragma unroll
        for (int ni = 0; ni < 4; ni++)
            #pragma unroll
            for (int q = 0; q < 4; q++) acc[mi][ni][q] = 0.f;

    GemmSrc S = {g_Xh, g_Xl, g_W1h, g_W1l, KX, KX};
    gemm_mainloop(sb, S, KX / 32, m0, n0, acc);

    #pragma unroll
    for (int mi = 0; mi < 4; mi++) {
        #pragma unroll
        for (int rr = 0; rr < 2; rr++) {
            int m = m0 + wm + mi * 16 + r + rr * 8;
            #pragma unroll
            for (int ni = 0; ni < 4; ni++) {
                int nn = n0 + wn + ni * 8 + cq;
                float x0 = acc[mi][ni][rr * 2 + 0] + b1[nn];
                float x1 = acc[mi][ni][rr * 2 + 1] + b1[nn + 1];
                float g0 = 0.5f * x0 * (1.0f + erff(x0 * 0.70710678118654752f));
                float g1 = 0.5f * x1 * (1.0f + erff(x1 * 0.70710678118654752f));
                __nv_bfloat16 h0 = __float2bfloat16(g0);
                __nv_bfloat16 h1 = __float2bfloat16(g1);
                __nv_bfloat16 l0 = __float2bfloat16(g0 - __bfloat162float(h0));
                __nv_bfloat16 l1 = __float2bfloat16(g1 - __bfloat162float(h1));
                __nv_bfloat162 ph = __halves2bfloat162(h0, h1);
                __nv_bfloat162 pl = __halves2bfloat162(l0, l1);
                *(uint32_t*)(g_Hh + (size_t)m * NH + nn) = *(uint32_t*)&ph;
                *(uint32_t*)(g_Hl + (size_t)m * NH + nn) = *(uint32_t*)&pl;
            }
        }
    }
}

__global__ void __launch_bounds__(256, 2) gemm2_mma(const float* __restrict__ b2,
                                                    float* __restrict__ out) {
    uint32_t sb = smem_u32(dynsm);
    const int m0 = blockIdx.y * 128, n0 = blockIdx.x * 128;
    const int lane = threadIdx.x & 31, wid = threadIdx.x >> 5;
    const int wm = (wid >> 2) * 64, wn = (wid & 3) * 32;
    const int r = lane >> 2, cq = (lane & 3) * 2;

    float acc[4][4][4];
    #pragma unroll
    for (int mi = 0; mi < 4; mi++)
        #pragma unroll
        for (int ni = 0; ni < 4; ni++)
            #pragma unroll
            for (int q = 0; q < 4; q++) acc[mi][ni][q] = 0.f;

    GemmSrc S = {g_Hh, g_Hl, g_W2h, g_W2l, NH, NH};
    gemm_mainloop(sb, S, NH / 32, m0, n0, acc);

    #pragma unroll
    for (int mi = 0; mi < 4; mi++) {
        #pragma unroll
        for (int rr = 0; rr < 2; rr++) {
            int m   = m0 + wm + mi * 16 + r + rr * 8;
            int n_  = m & 4095;
            int lvl = m >> 12;
            float* orow = out + (size_t)n_ * 1024 + lvl * 256;
            #pragma unroll
            for (int ni = 0; ni < 4; ni++) {
                int nn = n0 + wn + ni * 8 + cq;
                float2 o;
                o.x = acc[mi][ni][rr * 2 + 0] + b2[nn];
                o.y = acc[mi][ni][rr * 2 + 1] + b2[nn + 1];
                *(float2*)(orow + nn) = o;
            }
        }
    }
}

// =====================================================================
// Host launcher
// =====================================================================
extern "C" void kernel_launch(void* const* d_in, const int* in_sizes, int n_in,
                              void* d_out, int out_size) {
    const float *fm[4] = {0, 0, 0, 0}, *tf[4] = {0, 0, 0, 0};
    const float *coords = 0, *w1 = 0, *b1 = 0, *w2 = 0, *b2 = 0;
    int tfc = 0;

    auto isW2Neighbor = [](int s) { return s == 384 || s == 256 || s == 921984; };
    auto isFmNeighbor = [](int s) {
        return s == 1572864 || s == 393216 || s == 24576 || s == 25690112;
    };

    for (int i = 0; i < n_in; i++) {
        int s = in_sizes[i];
        const float* p = (const float*)d_in[i];
        switch (s) {
            case 1572864:  fm[0] = p; break;
            case 393216:   fm[1] = p; break;
            case 24576:    fm[3] = p; break;
            case 25690112: if (tfc < 4) tf[tfc++] = p; break;
            case 8192:     coords = p; break;
            case 921984:   w1 = p; break;
            case 384:      b1 = p; break;
            case 256:      b2 = p; break;
            case 98304: {
                int decided = 0;
                if (i > 0) {
                    if (isW2Neighbor(in_sizes[i - 1])) decided = 1;
                    else if (isFmNeighbor(in_sizes[i - 1])) decided = 2;
                }
                if (!decided && i + 1 < n_in) {
                    if (isW2Neighbor(in_sizes[i + 1])) decided = 1;
                    else if (isFmNeighbor(in_sizes[i + 1])) decided = 2;
                }
                if (decided == 1) w2 = p;
                else if (decided == 2) fm[2] = p;
                else { if (!fm[2]) fm[2] = p; else w2 = p; }
            } break;
            default: break;
        }
    }

    float* out = (float*)d_out;

    cudaFuncSetAttribute(corr_tc,   cudaFuncAttributeMaxDynamicSharedMemorySize, CSMEM);
    cudaFuncSetAttribute(gemm1_mma, cudaFuncAttributeMaxDynamicSharedMemorySize, GSMEM);
    cudaFuncSetAttribute(gemm2_mma, cudaFuncAttributeMaxDynamicSharedMemorySize, GSMEM);

    prep_kernel<<<PIX_TOT / 2 + NH + NO, 256>>>(fm[0], fm[1], fm[2], fm[3], w1, w2);
    corr_tc<<<MTOT, 256, CSMEM>>>(coords, tf[0], tf[1], tf[2], tf[3]);
    gemm1_mma<<<dim3(3, 128), 256, GSMEM>>>(b1);
    gemm2_mma<<<dim3(2, 128), 256, GSMEM>>>(b2, out);
}